// round 5
// baseline (speedup 1.0000x reference)
#include <cuda_runtime.h>
#include <cstdint>

#define HF 64
#define WF 64
#define CC 256
#define NB 4
#define KK 2048

// NHWC-transposed feature map scratch: [N][H][W][C] = 4*64*64*256 floats = 16 MB
__device__ float g_nhwc[NB * HF * WF * CC];

// ---------------------------------------------------------------------------
// Kernel 1: NCHW -> NHWC transpose via 32x32 smem tiles, coalesced both sides.
// ---------------------------------------------------------------------------
__global__ void transpose_nchw_nhwc(const float* __restrict__ in) {
    __shared__ float tile[32][33];
    const int n  = blockIdx.z;
    const int c0 = blockIdx.y * 32;
    const int s0 = blockIdx.x * 32;

    const float* inp = in + (size_t)n * CC * (HF * WF);
#pragma unroll
    for (int i = 0; i < 32; i += 8) {
        tile[threadIdx.y + i][threadIdx.x] =
            inp[(size_t)(c0 + threadIdx.y + i) * (HF * WF) + s0 + threadIdx.x];
    }
    __syncthreads();

    float* outp = g_nhwc + (size_t)n * (HF * WF) * CC;
#pragma unroll
    for (int i = 0; i < 32; i += 8) {
        outp[(size_t)(s0 + threadIdx.y + i) * CC + c0 + threadIdx.x] =
            tile[threadIdx.x][threadIdx.y + i];
    }
}

__device__ __forceinline__ float4 fmax4(float4 a, float4 b) {
    a.x = fmaxf(a.x, b.x);
    a.y = fmaxf(a.y, b.y);
    a.z = fmaxf(a.z, b.z);
    a.w = fmaxf(a.w, b.w);
    return a;
}

// ---------------------------------------------------------------------------
// Kernel 2: RoI max pool.
//   grid  = (4 channel-quarters, 2048 rois), block = 128 threads
//   thread t: channel group cg = t&15 (4 channels via float4),
//             bin slice   sl = t>>4 (8 slices x ~6 bins of the 49)
// Bin boundaries are block-uniform: computed once by 8 threads into smem.
// h-pair + w-pair inner loop keeps up to 4 independent LDGs in flight.
// ---------------------------------------------------------------------------
__global__ __launch_bounds__(128, 12)
void roipool_kernel(const float* __restrict__ rois, float* __restrict__ out) {
    __shared__ float sres[64 * 49];
    __shared__ int   sb[29];   // hs[0:7), he[7:14), ws[14:21), we[21:28), b[28]

    const int k   = blockIdx.y;
    const int q   = blockIdx.x;     // channel quarter (64 channels)
    const int tid = threadIdx.x;

    if (tid < 8) {
        const float* r = rois + (size_t)k * 5;
        if (tid == 7) {
            sb[28] = (int)r[0];
        } else {
            // round-half-even == jnp.round; reciprocal-multiply division
            // matches the reference's XLA lowering (verified: rel_err == 0).
            const int rsw = __float2int_rn(r[1] * 0.0625f);
            const int rsh = __float2int_rn(r[2] * 0.0625f);
            const int rew = __float2int_rn(r[3] * 0.0625f);
            const int reh = __float2int_rn(r[4] * 0.0625f);
            const float RCP7 = 1.0f / 7.0f;
            const float bin_h = (float)max(reh - rsh + 1, 1) * RCP7;
            const float bin_w = (float)max(rew - rsw + 1, 1) * RCP7;
            const int p = tid;   // 0..6
            sb[p]      = min(max((int)floorf((float)p * bin_h) + rsh, 0), HF);
            sb[7 + p]  = min(max((int)ceilf((float)(p + 1) * bin_h) + rsh, 0), HF);
            sb[14 + p] = min(max((int)floorf((float)p * bin_w) + rsw, 0), WF);
            sb[21 + p] = min(max((int)ceilf((float)(p + 1) * bin_w) + rsw, 0), WF);
        }
    }
    __syncthreads();

    const int cg = tid & 15;    // channel group within quarter
    const int sl = tid >> 4;    // bin slice 0..7

    // float4 view: cell (h,w), group g at (h*WF+w)*64 + g
    const float4* base =
        (const float4*)(g_nhwc + (size_t)sb[28] * (HF * WF) * CC) + (q * 16 + cg);

    const float NEG_INF = __int_as_float(0xff800000);

    int bi           = (49 * sl) >> 3;       // 6,6,6,6,6,6,6,7 bins/slice
    const int bi_end = (49 * (sl + 1)) >> 3;

    for (; bi < bi_end; ++bi) {
        const int ph = bi / 7;               // const-div -> mul/shift
        const int pw = bi - ph * 7;

        const int hs = sb[ph];
        const int he = sb[7 + ph];
        const int ws = sb[14 + pw];
        const int we = sb[21 + pw];
        const int wc = we - ws;

        float4 m0 = make_float4(NEG_INF, NEG_INF, NEG_INF, NEG_INF);
        float4 m1 = m0;

        const float4* p = base + (size_t)(hs * WF + ws) * 64;
        int h = hs;
        // h-pair: 2 rows concurrently, w-pair inside -> up to 4 loads in flight
        for (; h + 2 <= he; h += 2) {
            const float4* p1 = p + (size_t)WF * 64;
            int w = 0;
            for (; w + 2 <= wc; w += 2) {
                float4 a = __ldg(p  + (size_t)w * 64);
                float4 b = __ldg(p1 + (size_t)w * 64);
                float4 c = __ldg(p  + (size_t)(w + 1) * 64);
                float4 d = __ldg(p1 + (size_t)(w + 1) * 64);
                m0 = fmax4(fmax4(m0, a), c);
                m1 = fmax4(fmax4(m1, b), d);
            }
            if (w < wc) {
                m0 = fmax4(m0, __ldg(p  + (size_t)w * 64));
                m1 = fmax4(m1, __ldg(p1 + (size_t)w * 64));
            }
            p += (size_t)2 * WF * 64;
        }
        if (h < he) {   // odd remainder row
            int w = 0;
            for (; w + 2 <= wc; w += 2) {
                float4 a = __ldg(p + (size_t)w * 64);
                float4 c = __ldg(p + (size_t)(w + 1) * 64);
                m0 = fmax4(m0, a);
                m1 = fmax4(m1, c);
            }
            if (w < wc) m0 = fmax4(m0, __ldg(p + (size_t)w * 64));
        }

        float4 m = fmax4(m0, m1);
        if (!((hs < he) && (ws < we)))
            m = make_float4(0.f, 0.f, 0.f, 0.f);

        const int cbase = 4 * cg;
        sres[(cbase + 0) * 49 + bi] = m.x;
        sres[(cbase + 1) * 49 + bi] = m.y;
        sres[(cbase + 2) * 49 + bi] = m.z;
        sres[(cbase + 3) * 49 + bi] = m.w;
    }
    __syncthreads();

    // Contiguous coalesced flush: this block owns output span
    // [k*12544 + q*3136, +3136) = 784 float4.
    float4* outv = (float4*)(out + (size_t)k * (CC * 49) + (size_t)q * (64 * 49));
    const float4* sv = (const float4*)sres;
#pragma unroll
    for (int i = 0; i < 6; ++i) {
        int t = tid + i * 128;
        outv[t] = sv[t];
    }
    if (tid < 784 - 6 * 128) {
        int t = tid + 6 * 128;
        outv[t] = sv[t];
    }
}

extern "C" void kernel_launch(void* const* d_in, const int* in_sizes, int n_in,
                              void* d_out, int out_size) {
    const float* input = (const float*)d_in[0];   // [4,256,64,64] fp32
    const float* rois  = (const float*)d_in[1];   // [2048,5] fp32
    float* out = (float*)d_out;                   // [2048,256,7,7] fp32

    dim3 tgrid((HF * WF) / 32, CC / 32, NB);      // (128, 8, 4)
    transpose_nchw_nhwc<<<tgrid, dim3(32, 8)>>>(input);

    roipool_kernel<<<dim3(4, KK), 128>>>(rois, out);
}

// round 6
// speedup vs baseline: 1.0529x; 1.0529x over previous
#include <cuda_runtime.h>
#include <cstdint>

#define HF 64
#define WF 64
#define CC 256
#define NB 4
#define KK 2048

// NHWC-transposed feature map scratch: [N][H][W][C] = 4*64*64*256 floats = 16 MB
__device__ float g_nhwc[NB * HF * WF * CC];

// ---------------------------------------------------------------------------
// Kernel 1: NCHW -> NHWC transpose via 32x32 smem tiles, coalesced both sides.
// ---------------------------------------------------------------------------
__global__ void transpose_nchw_nhwc(const float* __restrict__ in) {
    __shared__ float tile[32][33];
    const int n  = blockIdx.z;
    const int c0 = blockIdx.y * 32;
    const int s0 = blockIdx.x * 32;

    const float* inp = in + (size_t)n * CC * (HF * WF);
#pragma unroll
    for (int i = 0; i < 32; i += 8) {
        tile[threadIdx.y + i][threadIdx.x] =
            inp[(size_t)(c0 + threadIdx.y + i) * (HF * WF) + s0 + threadIdx.x];
    }
    __syncthreads();

    float* outp = g_nhwc + (size_t)n * (HF * WF) * CC;
#pragma unroll
    for (int i = 0; i < 32; i += 8) {
        outp[(size_t)(s0 + threadIdx.y + i) * CC + c0 + threadIdx.x] =
            tile[threadIdx.x][threadIdx.y + i];
    }
}

__device__ __forceinline__ float4 fmax4(float4 a, float4 b) {
    a.x = fmaxf(a.x, b.x);
    a.y = fmaxf(a.y, b.y);
    a.z = fmaxf(a.z, b.z);
    a.w = fmaxf(a.w, b.w);
    return a;
}

// ---------------------------------------------------------------------------
// Kernel 2: RoI max pool.
//   grid  = (2 channel-halves, 2048 rois), block = 256 threads
//   thread t: channel group cg = t&31 (4 channels via float4),
//             bin slice   sl = t>>5 (WARP-UNIFORM: one warp per slice)
// Bin boundaries are block-uniform -> computed once by 8 threads into smem.
// h-pair + w-pair inner loop keeps up to 4 independent LDGs in flight.
// A warp's LDG covers 32 consecutive float4 = 512B, fully coalesced.
// ---------------------------------------------------------------------------
__global__ __launch_bounds__(256, 6)
void roipool_kernel(const float* __restrict__ rois, float* __restrict__ out) {
    __shared__ float sres[128 * 49];
    __shared__ int   sb[29];   // hs[0:7), he[7:14), ws[14:21), we[21:28), b[28]

    const int k    = blockIdx.y;
    const int half = blockIdx.x;
    const int tid  = threadIdx.x;

    if (tid < 8) {
        const float* r = rois + (size_t)k * 5;
        if (tid == 7) {
            sb[28] = (int)r[0];
        } else {
            // round-half-even == jnp.round; reciprocal-multiply division
            // matches the reference's XLA lowering (verified: rel_err == 0).
            const int rsw = __float2int_rn(r[1] * 0.0625f);
            const int rsh = __float2int_rn(r[2] * 0.0625f);
            const int rew = __float2int_rn(r[3] * 0.0625f);
            const int reh = __float2int_rn(r[4] * 0.0625f);
            const float RCP7 = 1.0f / 7.0f;
            const float bin_h = (float)max(reh - rsh + 1, 1) * RCP7;
            const float bin_w = (float)max(rew - rsw + 1, 1) * RCP7;
            const int p = tid;   // 0..6
            sb[p]      = min(max((int)floorf((float)p * bin_h) + rsh, 0), HF);
            sb[7 + p]  = min(max((int)ceilf((float)(p + 1) * bin_h) + rsh, 0), HF);
            sb[14 + p] = min(max((int)floorf((float)p * bin_w) + rsw, 0), WF);
            sb[21 + p] = min(max((int)ceilf((float)(p + 1) * bin_w) + rsw, 0), WF);
        }
    }
    __syncthreads();

    const int cg = tid & 31;    // channel group (warp-contiguous)
    const int sl = tid >> 5;    // bin slice, uniform across the warp

    // float4 view: cell (h,w), group g at (h*WF+w)*64 + g
    const float4* base =
        (const float4*)(g_nhwc + (size_t)sb[28] * (HF * WF) * CC) + (half * 32 + cg);

    const float NEG_INF = __int_as_float(0xff800000);

    int bi           = (49 * sl) >> 3;       // 6,6,6,6,6,6,6,7 bins/slice
    const int bi_end = (49 * (sl + 1)) >> 3;

    for (; bi < bi_end; ++bi) {
        const int ph = bi / 7;               // const-div -> mul/shift
        const int pw = bi - ph * 7;

        const int hs = sb[ph];
        const int he = sb[7 + ph];
        const int ws = sb[14 + pw];
        const int we = sb[21 + pw];
        const int wc = we - ws;

        float4 m0 = make_float4(NEG_INF, NEG_INF, NEG_INF, NEG_INF);
        float4 m1 = m0;

        const float4* p = base + (size_t)(hs * WF + ws) * 64;
        int h = hs;
        // h-pair: 2 rows concurrently, w-pair inside -> up to 4 loads in flight
        for (; h + 2 <= he; h += 2) {
            const float4* p1 = p + (size_t)WF * 64;
            int w = 0;
            for (; w + 2 <= wc; w += 2) {
                float4 a = __ldg(p  + (size_t)w * 64);
                float4 b = __ldg(p1 + (size_t)w * 64);
                float4 c = __ldg(p  + (size_t)(w + 1) * 64);
                float4 d = __ldg(p1 + (size_t)(w + 1) * 64);
                m0 = fmax4(fmax4(m0, a), c);
                m1 = fmax4(fmax4(m1, b), d);
            }
            if (w < wc) {
                m0 = fmax4(m0, __ldg(p  + (size_t)w * 64));
                m1 = fmax4(m1, __ldg(p1 + (size_t)w * 64));
            }
            p += (size_t)2 * WF * 64;
        }
        if (h < he) {   // odd remainder row
            int w = 0;
            for (; w + 2 <= wc; w += 2) {
                float4 a = __ldg(p + (size_t)w * 64);
                float4 c = __ldg(p + (size_t)(w + 1) * 64);
                m0 = fmax4(m0, a);
                m1 = fmax4(m1, c);
            }
            if (w < wc) m0 = fmax4(m0, __ldg(p + (size_t)w * 64));
        }

        float4 m = fmax4(m0, m1);
        if (!((hs < he) && (ws < we)))
            m = make_float4(0.f, 0.f, 0.f, 0.f);

        const int cbase = 4 * cg;
        sres[(cbase + 0) * 49 + bi] = m.x;
        sres[(cbase + 1) * 49 + bi] = m.y;
        sres[(cbase + 2) * 49 + bi] = m.z;
        sres[(cbase + 3) * 49 + bi] = m.w;
    }
    __syncthreads();

    // Contiguous coalesced flush: this block owns output span
    // [k*12544 + half*6272, +6272) = 1568 float4.
    float4* outv = (float4*)(out + (size_t)k * (CC * 49) + (size_t)half * (128 * 49));
    const float4* sv = (const float4*)sres;
#pragma unroll
    for (int i = 0; i < 6; ++i) {
        int t = tid + i * 256;
        outv[t] = sv[t];
    }
    if (tid < 1568 - 6 * 256) {
        int t = tid + 6 * 256;
        outv[t] = sv[t];
    }
}

extern "C" void kernel_launch(void* const* d_in, const int* in_sizes, int n_in,
                              void* d_out, int out_size) {
    const float* input = (const float*)d_in[0];   // [4,256,64,64] fp32
    const float* rois  = (const float*)d_in[1];   // [2048,5] fp32
    float* out = (float*)d_out;                   // [2048,256,7,7] fp32

    dim3 tgrid((HF * WF) / 32, CC / 32, NB);      // (128, 8, 4)
    transpose_nchw_nhwc<<<tgrid, dim3(32, 8)>>>(input);

    roipool_kernel<<<dim3(2, KK), 256>>>(rois, out);
}